// round 7
// baseline (speedup 1.0000x reference)
#include <cuda_runtime.h>
#include <cstdint>

// Model_25855703122577: inputs [8192,784,1] f32, W_ih[30,1], W_hh[30,30],
// b_mod[30], W_lin[10,30], b_lin[10] -> out [8192,10] f32
#define RB    8192
#define RT    784
#define RH    30
#define RC    10
#define GRP   8        // lanes per batch element
#define RPT   4        // rows per lane (8*4 = 32 >= 30)
#define KP    15       // k-pairs (exact)
#define NCH   8        // 16B h chunks per slot (chunk 7 = pairs 14 + zero pad)
#define TPB   32       // one warp per block
#define SLOTS 4        // batch slots per warp
#define HSTR  36       // floats per slot (144B = 9*16B: aligned, banks shift 4)

typedef unsigned long long u64;

__device__ __forceinline__ u64 fmul2(u64 a, u64 b) {
    u64 d; asm("mul.rn.f32x2 %0, %1, %2;" : "=l"(d) : "l"(a), "l"(b)); return d;
}
__device__ __forceinline__ u64 ffma2(u64 a, u64 b, u64 c) {
    u64 d; asm("fma.rn.f32x2 %0, %1, %2, %3;" : "=l"(d) : "l"(a), "l"(b), "l"(c)); return d;
}
__device__ __forceinline__ void unpack2(u64 v, float& lo, float& hi) {
    asm("mov.b64 {%0, %1}, %2;" : "=f"(lo), "=f"(hi) : "l"(v));
}

// One recurrence step for this lane's 4 rows. h loaded as 8 LDS.128 chunks
// interleaved into the FFMA2 chain (ring, prefetch distance 2) so the issue
// stream has no load burst -> warps can overlap instead of convoying.
__device__ __forceinline__ void rnn_step(
    float x,
    const u64 (&w)[RPT][KP],
    const float (&wih)[RPT],
    const float (&bm)[RPT],
    const float* __restrict__ hsrc,   // slot base (32 floats, pads zero)
    float* __restrict__ hdst)         // other buffer, this lane's float4
{
    const ulonglong2* hp = reinterpret_cast<const ulonglong2*>(hsrc);

    ulonglong2 rb0 = hp[0];
    ulonglong2 rb1 = hp[1];

    u64 acc[RPT];
    // chunk 0 (pairs 0,1): start 4 chains
#pragma unroll
    for (int r = 0; r < RPT; r++) {
        acc[r] = fmul2(w[r][0], rb0.x);
        acc[r] = ffma2(w[r][1], rb0.y, acc[r]);
    }
    rb0 = hp[2];
    // chunk 1 (pairs 2,3)
#pragma unroll
    for (int r = 0; r < RPT; r++) {
        acc[r] = ffma2(w[r][2], rb1.x, acc[r]);
        acc[r] = ffma2(w[r][3], rb1.y, acc[r]);
    }
    rb1 = hp[3];
    // chunk 2
#pragma unroll
    for (int r = 0; r < RPT; r++) {
        acc[r] = ffma2(w[r][4], rb0.x, acc[r]);
        acc[r] = ffma2(w[r][5], rb0.y, acc[r]);
    }
    rb0 = hp[4];
    // chunk 3
#pragma unroll
    for (int r = 0; r < RPT; r++) {
        acc[r] = ffma2(w[r][6], rb1.x, acc[r]);
        acc[r] = ffma2(w[r][7], rb1.y, acc[r]);
    }
    rb1 = hp[5];
    // chunk 4
#pragma unroll
    for (int r = 0; r < RPT; r++) {
        acc[r] = ffma2(w[r][8], rb0.x, acc[r]);
        acc[r] = ffma2(w[r][9], rb0.y, acc[r]);
    }
    rb0 = hp[6];
    // chunk 5
#pragma unroll
    for (int r = 0; r < RPT; r++) {
        acc[r] = ffma2(w[r][10], rb1.x, acc[r]);
        acc[r] = ffma2(w[r][11], rb1.y, acc[r]);
    }
    rb1 = hp[7];
    // chunk 6
#pragma unroll
    for (int r = 0; r < RPT; r++) {
        acc[r] = ffma2(w[r][12], rb0.x, acc[r]);
        acc[r] = ffma2(w[r][13], rb0.y, acc[r]);
    }
    // chunk 7: pair 14 only (pair 15 is the zero pad -> skipped)
#pragma unroll
    for (int r = 0; r < RPT; r++) {
        acc[r] = ffma2(w[r][14], rb1.x, acc[r]);
    }

    float hv[RPT];
#pragma unroll
    for (int r = 0; r < RPT; r++) {
        float lo, hi;
        unpack2(acc[r], lo, hi);
        float z = fmaf(x, wih[r], lo + hi);
        // modReLU: copysign(relu(|z|+b), z). (z==0 exact is measure-zero;
        // pad rows have w=wih=b=0 -> z=0 -> copysign(relu(0),+0)=+0: stays 0.)
        float m = fmaxf(fabsf(z) + bm[r], 0.0f);
        hv[r] = copysignf(m, z);
    }
    *reinterpret_cast<float4*>(hdst) = make_float4(hv[0], hv[1], hv[2], hv[3]);
    __syncwarp();
}

extern "C" __global__ void __launch_bounds__(TPB, 13)
rnn_modrelu_kernel(const float* __restrict__ inputs,  // [B, T]
                   const float* __restrict__ W_ih,    // [H]
                   const float* __restrict__ W_hh,    // [H, H]
                   const float* __restrict__ b_mod,   // [H]
                   const float* __restrict__ W_lin,   // [C, H]
                   const float* __restrict__ b_lin,   // [C]
                   float* __restrict__ out)           // [B, C]
{
    __shared__ __align__(16) float hbuf[2][SLOTS][HSTR];

    const int tid = threadIdx.x;        // 0..31
    const int sub = tid & (GRP - 1);    // 0..7 row-slice
    const int s   = tid >> 3;           // 0..3 batch slot
    const int b   = blockIdx.x * SLOTS + s;

    // ---- register-resident weight slice ----
    u64 w[RPT][KP];
    float wih[RPT], bm[RPT];
#pragma unroll
    for (int r = 0; r < RPT; r++) {
        const int row = sub * RPT + r;
        if (row < RH) {
            const u64* wr = reinterpret_cast<const u64*>(W_hh + row * RH);
#pragma unroll
            for (int p = 0; p < KP; p++) w[r][p] = wr[p];
            wih[r] = W_ih[row];
            bm[r]  = b_mod[row];
        } else {            // pad rows 30,31: stay exactly 0 forever
#pragma unroll
            for (int p = 0; p < KP; p++) w[r][p] = 0ULL;
            wih[r] = 0.0f;
            bm[r]  = 0.0f;
        }
    }

    // h0 = 0 (incl. pad floats 30,31; floats 32..35 never read)
    *reinterpret_cast<float4*>(&hbuf[0][s][sub * 4]) = make_float4(0, 0, 0, 0);
    __syncwarp();

    const float* xr = inputs + (size_t)b * RT;

#pragma unroll 1
    for (int t0 = 0; t0 < RT; t0 += 4) {
        const float4 x4 = *reinterpret_cast<const float4*>(xr + t0);
        rnn_step(x4.x, w, wih, bm, &hbuf[0][s][0], &hbuf[1][s][sub * 4]);
        rnn_step(x4.y, w, wih, bm, &hbuf[1][s][0], &hbuf[0][s][sub * 4]);
        rnn_step(x4.z, w, wih, bm, &hbuf[0][s][0], &hbuf[1][s][sub * 4]);
        rnn_step(x4.w, w, wih, bm, &hbuf[1][s][0], &hbuf[0][s][sub * 4]);
    }
    // T=784 even -> final h in buffer 0

    // ---- fused classifier: out[b][c] = h . W_lin[c] + b_lin[c] ----
    const float* hf = &hbuf[0][s][0];
#pragma unroll 1
    for (int c = sub; c < RC; c += GRP) {
        float acc = b_lin[c];
        const float* wl = W_lin + c * RH;
#pragma unroll
        for (int k = 0; k < RH; k++) acc = fmaf(hf[k], wl[k], acc);
        out[(size_t)b * RC + c] = acc;
    }
}

extern "C" void kernel_launch(void* const* d_in, const int* in_sizes, int n_in,
                              void* d_out, int out_size) {
    const float* inputs = (const float*)d_in[0];
    const float* W_ih   = (const float*)d_in[1];
    const float* W_hh   = (const float*)d_in[2];
    const float* b_mod  = (const float*)d_in[3];
    const float* W_lin  = (const float*)d_in[4];
    const float* b_lin  = (const float*)d_in[5];
    float* out = (float*)d_out;

    dim3 grid(RB / SLOTS);   // 2048 one-warp blocks; 13/SM -> 6.4% wave tail
    dim3 block(TPB);
    rnn_modrelu_kernel<<<grid, block>>>(inputs, W_ih, W_hh, b_mod,
                                        W_lin, b_lin, out);
}

// round 8
// speedup vs baseline: 1.0035x; 1.0035x over previous
#include <cuda_runtime.h>
#include <cstdint>

// Model_25855703122577: inputs [8192,784,1] f32, W_ih[30,1], W_hh[30,30],
// b_mod[30], W_lin[10,30], b_lin[10] -> out [8192,10] f32
#define RB    8192
#define RT    784
#define RH    30
#define RC    10
#define GRP   8        // lanes per batch element
#define RPT   4        // rows per lane (8*4 = 32 >= 30, 2 zero pad rows)
#define KP    15       // k-pairs (exact)
#define TPB   64       // two warps per block
#define BPB   8        // batch slots per block (4 per warp)
#define HSTR  36       // floats per slot (144B: 16B-aligned, banks shift 4/slot)

typedef unsigned long long u64;

__device__ __forceinline__ u64 fmul2(u64 a, u64 b) {
    u64 d; asm("mul.rn.f32x2 %0, %1, %2;" : "=l"(d) : "l"(a), "l"(b)); return d;
}
__device__ __forceinline__ u64 ffma2(u64 a, u64 b, u64 c) {
    u64 d; asm("fma.rn.f32x2 %0, %1, %2, %3;" : "=l"(d) : "l"(a), "l"(b), "l"(c)); return d;
}
__device__ __forceinline__ void unpack2(u64 v, float& lo, float& hi) {
    asm("mov.b64 {%0, %1}, %2;" : "=f"(lo), "=f"(hi) : "l"(v));
}

// One step, 4 rows. h read as 8 LDS.128 chunks streamed through a 2-deep
// ring interleaved with the FFMA2 chains (no load burst, live set = 8 regs).
__device__ __forceinline__ void rnn_step(
    float x,
    const u64 (&w)[RPT][KP],
    const float (&wih)[RPT],
    const float (&bm)[RPT],
    const float* __restrict__ hsrc,   // slot base (32 floats, pads zero)
    float* __restrict__ hdst)         // other buffer, this lane's float4
{
    const ulonglong2* hp = reinterpret_cast<const ulonglong2*>(hsrc);

    ulonglong2 rb0 = hp[0];
    ulonglong2 rb1 = hp[1];

    u64 acc[RPT];
#pragma unroll
    for (int r = 0; r < RPT; r++) {
        acc[r] = fmul2(w[r][0], rb0.x);
        acc[r] = ffma2(w[r][1], rb0.y, acc[r]);
    }
    rb0 = hp[2];
#pragma unroll
    for (int r = 0; r < RPT; r++) {
        acc[r] = ffma2(w[r][2], rb1.x, acc[r]);
        acc[r] = ffma2(w[r][3], rb1.y, acc[r]);
    }
    rb1 = hp[3];
#pragma unroll
    for (int r = 0; r < RPT; r++) {
        acc[r] = ffma2(w[r][4], rb0.x, acc[r]);
        acc[r] = ffma2(w[r][5], rb0.y, acc[r]);
    }
    rb0 = hp[4];
#pragma unroll
    for (int r = 0; r < RPT; r++) {
        acc[r] = ffma2(w[r][6], rb1.x, acc[r]);
        acc[r] = ffma2(w[r][7], rb1.y, acc[r]);
    }
    rb1 = hp[5];
#pragma unroll
    for (int r = 0; r < RPT; r++) {
        acc[r] = ffma2(w[r][8], rb0.x, acc[r]);
        acc[r] = ffma2(w[r][9], rb0.y, acc[r]);
    }
    rb0 = hp[6];
#pragma unroll
    for (int r = 0; r < RPT; r++) {
        acc[r] = ffma2(w[r][10], rb1.x, acc[r]);
        acc[r] = ffma2(w[r][11], rb1.y, acc[r]);
    }
    rb1 = hp[7];
#pragma unroll
    for (int r = 0; r < RPT; r++) {
        acc[r] = ffma2(w[r][12], rb0.x, acc[r]);
        acc[r] = ffma2(w[r][13], rb0.y, acc[r]);
    }
#pragma unroll
    for (int r = 0; r < RPT; r++) {     // pair 14 (pair 15 = zero pad, skip)
        acc[r] = ffma2(w[r][14], rb1.x, acc[r]);
    }

    float hv[RPT];
#pragma unroll
    for (int r = 0; r < RPT; r++) {
        float lo, hi;
        unpack2(acc[r], lo, hi);
        float z = fmaf(x, wih[r], lo + hi);
        // modReLU: copysign(relu(|z|+b), z); z==0 exact -> +0 (pad rows stay 0)
        float m = fmaxf(fabsf(z) + bm[r], 0.0f);
        hv[r] = copysignf(m, z);
    }
    *reinterpret_cast<float4*>(hdst) = make_float4(hv[0], hv[1], hv[2], hv[3]);
    __syncwarp();
}

extern "C" __global__ void __launch_bounds__(TPB, 7)
rnn_modrelu_kernel(const float* __restrict__ inputs,  // [B, T]
                   const float* __restrict__ W_ih,    // [H]
                   const float* __restrict__ W_hh,    // [H, H]
                   const float* __restrict__ b_mod,   // [H]
                   const float* __restrict__ W_lin,   // [C, H]
                   const float* __restrict__ b_lin,   // [C]
                   float* __restrict__ out)           // [B, C]
{
    __shared__ __align__(16) float hbuf[2][BPB][HSTR];

    const int tid = threadIdx.x;        // 0..63
    const int sub = tid & (GRP - 1);    // 0..7 row-slice
    const int s   = tid >> 3;           // 0..7 batch slot (warp0: 0-3, warp1: 4-7)
    const int b   = blockIdx.x * BPB + s;

    // ---- register-resident weight slice ----
    u64 w[RPT][KP];
    float wih[RPT], bm[RPT];
#pragma unroll
    for (int r = 0; r < RPT; r++) {
        const int row = sub * RPT + r;
        if (row < RH) {
            const u64* wr = reinterpret_cast<const u64*>(W_hh + row * RH);
#pragma unroll
            for (int p = 0; p < KP; p++) w[r][p] = wr[p];
            wih[r] = W_ih[row];
            bm[r]  = b_mod[row];
        } else {            // pad rows 30,31: all-zero, stay 0 forever
#pragma unroll
            for (int p = 0; p < KP; p++) w[r][p] = 0ULL;
            wih[r] = 0.0f;
            bm[r]  = 0.0f;
        }
    }

    // h0 = 0
    *reinterpret_cast<float4*>(&hbuf[0][s][sub * 4]) = make_float4(0, 0, 0, 0);
    __syncwarp();

    // ---- phase skew: stagger co-resident warps so their LDS/FMA phases
    // interleave instead of convoying. One-time dependent-FMA delay chain.
    {
        const int skew = ((blockIdx.x * 2 + (tid >> 5)) % 6) * 12;  // 0..60 links
        float d = 0.25f;
#pragma unroll 1
        for (int i = 0; i < skew; i++) d = fmaf(d, 1.0000001f, 0.5f);
        if (d < 0.0f) out[0] = d;   // chain stays positive: never taken,
                                    // but compiler must keep the chain
    }

    const float* xr = inputs + (size_t)b * RT;

#pragma unroll 1
    for (int t0 = 0; t0 < RT; t0 += 4) {
        const float4 x4 = *reinterpret_cast<const float4*>(xr + t0);
        rnn_step(x4.x, w, wih, bm, &hbuf[0][s][0], &hbuf[1][s][sub * 4]);
        rnn_step(x4.y, w, wih, bm, &hbuf[1][s][0], &hbuf[0][s][sub * 4]);
        rnn_step(x4.z, w, wih, bm, &hbuf[0][s][0], &hbuf[1][s][sub * 4]);
        rnn_step(x4.w, w, wih, bm, &hbuf[1][s][0], &hbuf[0][s][sub * 4]);
    }
    // T=784 even -> final h in buffer 0

    // ---- fused classifier: out[b][c] = h . W_lin[c] + b_lin[c] ----
    const float* hf = &hbuf[0][s][0];
#pragma unroll 1
    for (int c = sub; c < RC; c += GRP) {
        float acc = b_lin[c];
        const float* wl = W_lin + c * RH;
#pragma unroll
        for (int k = 0; k < RH; k++) acc = fmaf(hf[k], wl[k], acc);
        out[(size_t)b * RC + c] = acc;
    }
}

extern "C" void kernel_launch(void* const* d_in, const int* in_sizes, int n_in,
                              void* d_out, int out_size) {
    const float* inputs = (const float*)d_in[0];
    const float* W_ih   = (const float*)d_in[1];
    const float* W_hh   = (const float*)d_in[2];
    const float* b_mod  = (const float*)d_in[3];
    const float* W_lin  = (const float*)d_in[4];
    const float* b_lin  = (const float*)d_in[5];
    float* out = (float*)d_out;

    dim3 grid(RB / BPB);   // 1024 blocks x 2 warps; 7 blocks/SM -> single wave
    dim3 block(TPB);
    rnn_modrelu_kernel<<<grid, block>>>(inputs, W_ih, W_hh, b_mod,
                                        W_lin, b_lin, out);
}

// round 9
// speedup vs baseline: 1.6359x; 1.6302x over previous
#include <cuda_runtime.h>
#include <cstdint>

// Model_25855703122577: inputs [8192,784,1] f32, W_ih[30,1], W_hh[30,30],
// b_mod[30], W_lin[10,30], b_lin[10] -> out [8192,10] f32
#define RB    8192
#define RT    784
#define RH    30
#define RC    10
#define GRP   16       // lanes per batch element (2 groups per warp)
#define RPT   2        // rows per lane (16*2 = 32 >= 30, rows 30/31 pad)
#define KP    15       // k-pairs (exact)
#define TPB   32       // one warp per block
#define SLOTS 2        // batches per warp
#define HSTR  36       // floats per slot (144B, 16B-aligned)

typedef unsigned long long u64;

__device__ __forceinline__ u64 fmul2(u64 a, u64 b) {
    u64 d; asm("mul.rn.f32x2 %0, %1, %2;" : "=l"(d) : "l"(a), "l"(b)); return d;
}
__device__ __forceinline__ u64 ffma2(u64 a, u64 b, u64 c) {
    u64 d; asm("fma.rn.f32x2 %0, %1, %2, %3;" : "=l"(d) : "l"(a), "l"(b), "l"(c)); return d;
}
__device__ __forceinline__ void unpack2(u64 v, float& lo, float& hi) {
    asm("mov.b64 {%0, %1}, %2;" : "=f"(lo), "=f"(hi) : "l"(v));
}

// One step: this lane's 2 rows of its group's batch. h read as 8 LDS.128
// chunks through a 2-deep ring interleaved with the 2 FFMA2 chains.
__device__ __forceinline__ void rnn_step(
    float x,
    const u64 (&w)[RPT][KP],
    const float (&wih)[RPT],
    const float (&bm)[RPT],
    const float* __restrict__ hsrc,   // group slot base (32 floats, pads 0)
    float* __restrict__ hdst)         // other buffer, this lane's float2
{
    const ulonglong2* hp = reinterpret_cast<const ulonglong2*>(hsrc);

    ulonglong2 rb0 = hp[0];
    ulonglong2 rb1 = hp[1];

    u64 a0, a1;
    a0 = fmul2(w[0][0], rb0.x);  a1 = fmul2(w[1][0], rb0.x);
    a0 = ffma2(w[0][1], rb0.y, a0);  a1 = ffma2(w[1][1], rb0.y, a1);
    rb0 = hp[2];
    a0 = ffma2(w[0][2], rb1.x, a0);  a1 = ffma2(w[1][2], rb1.x, a1);
    a0 = ffma2(w[0][3], rb1.y, a0);  a1 = ffma2(w[1][3], rb1.y, a1);
    rb1 = hp[3];
    a0 = ffma2(w[0][4], rb0.x, a0);  a1 = ffma2(w[1][4], rb0.x, a1);
    a0 = ffma2(w[0][5], rb0.y, a0);  a1 = ffma2(w[1][5], rb0.y, a1);
    rb0 = hp[4];
    a0 = ffma2(w[0][6], rb1.x, a0);  a1 = ffma2(w[1][6], rb1.x, a1);
    a0 = ffma2(w[0][7], rb1.y, a0);  a1 = ffma2(w[1][7], rb1.y, a1);
    rb1 = hp[5];
    a0 = ffma2(w[0][8], rb0.x, a0);  a1 = ffma2(w[1][8], rb0.x, a1);
    a0 = ffma2(w[0][9], rb0.y, a0);  a1 = ffma2(w[1][9], rb0.y, a1);
    rb0 = hp[6];
    a0 = ffma2(w[0][10], rb1.x, a0);  a1 = ffma2(w[1][10], rb1.x, a1);
    a0 = ffma2(w[0][11], rb1.y, a0);  a1 = ffma2(w[1][11], rb1.y, a1);
    rb1 = hp[7];
    a0 = ffma2(w[0][12], rb0.x, a0);  a1 = ffma2(w[1][12], rb0.x, a1);
    a0 = ffma2(w[0][13], rb0.y, a0);  a1 = ffma2(w[1][13], rb0.y, a1);
    a0 = ffma2(w[0][14], rb1.x, a0);  a1 = ffma2(w[1][14], rb1.x, a1);
    // pair 15 = zero pad: skipped

    float lo0, hi0, lo1, hi1;
    unpack2(a0, lo0, hi0);
    unpack2(a1, lo1, hi1);
    float z0 = fmaf(x, wih[0], lo0 + hi0);
    float z1 = fmaf(x, wih[1], lo1 + hi1);
    // modReLU: copysign(relu(|z|+b), z); z==0 -> +0 (pad rows stay 0 forever)
    float m0 = fmaxf(fabsf(z0) + bm[0], 0.0f);
    float m1 = fmaxf(fabsf(z1) + bm[1], 0.0f);
    *reinterpret_cast<float2*>(hdst) =
        make_float2(copysignf(m0, z0), copysignf(m1, z1));
    __syncwarp();
}

extern "C" __global__ void __launch_bounds__(TPB)
rnn_modrelu_kernel(const float* __restrict__ inputs,  // [B, T]
                   const float* __restrict__ W_ih,    // [H]
                   const float* __restrict__ W_hh,    // [H, H]
                   const float* __restrict__ b_mod,   // [H]
                   const float* __restrict__ W_lin,   // [C, H]
                   const float* __restrict__ b_lin,   // [C]
                   float* __restrict__ out)           // [B, C]
{
    __shared__ __align__(16) float hbuf[2][SLOTS][HSTR];

    const int tid = threadIdx.x;        // 0..31
    const int sub = tid & (GRP - 1);    // 0..15 row-slice
    const int grp = tid >> 4;           // 0..1 batch group
    const int b   = blockIdx.x * SLOTS + grp;

    // ---- register weight slice: 2 rows x 15 pairs = 60 regs ----
    u64 w[RPT][KP];
    float wih[RPT], bm[RPT];
#pragma unroll
    for (int r = 0; r < RPT; r++) {
        const int row = sub * RPT + r;
        if (row < RH) {
            const u64* wr = reinterpret_cast<const u64*>(W_hh + row * RH);
#pragma unroll
            for (int p = 0; p < KP; p++) w[r][p] = wr[p];
            wih[r] = W_ih[row];
            bm[r]  = b_mod[row];
        } else {            // rows 30,31: all-zero, h pads stay exactly 0
#pragma unroll
            for (int p = 0; p < KP; p++) w[r][p] = 0ULL;
            wih[r] = 0.0f;
            bm[r]  = 0.0f;
        }
    }

    // h0 = 0 (each lane zeroes its float2 -> all 32 floats covered)
    *reinterpret_cast<float2*>(&hbuf[0][grp][sub * 2]) = make_float2(0, 0);
    __syncwarp();

    const float* xr = inputs + (size_t)b * RT;

#pragma unroll 1
    for (int t0 = 0; t0 < RT; t0 += 4) {
        const float4 x4 = *reinterpret_cast<const float4*>(xr + t0);
        rnn_step(x4.x, w, wih, bm, &hbuf[0][grp][0], &hbuf[1][grp][sub * 2]);
        rnn_step(x4.y, w, wih, bm, &hbuf[1][grp][0], &hbuf[0][grp][sub * 2]);
        rnn_step(x4.z, w, wih, bm, &hbuf[0][grp][0], &hbuf[1][grp][sub * 2]);
        rnn_step(x4.w, w, wih, bm, &hbuf[1][grp][0], &hbuf[0][grp][sub * 2]);
    }
    // T=784 even -> final h in buffer 0

    // ---- fused classifier: out[b][c] = h . W_lin[c] + b_lin[c] ----
    const float* hf = &hbuf[0][grp][0];
    if (sub < RC) {
        float acc = b_lin[sub];
        const float* wl = W_lin + sub * RH;
#pragma unroll
        for (int k = 0; k < RH; k++) acc = fmaf(hf[k], wl[k], acc);
        out[(size_t)b * RC + sub] = acc;
    }
}

extern "C" void kernel_launch(void* const* d_in, const int* in_sizes, int n_in,
                              void* d_out, int out_size) {
    const float* inputs = (const float*)d_in[0];
    const float* W_ih   = (const float*)d_in[1];
    const float* W_hh   = (const float*)d_in[2];
    const float* b_mod  = (const float*)d_in[3];
    const float* W_lin  = (const float*)d_in[4];
    const float* b_lin  = (const float*)d_in[5];
    float* out = (float*)d_out;

    dim3 grid(RB / SLOTS);   // 4096 one-warp blocks: ~25-27 warps/SM resident
    dim3 block(TPB);
    rnn_modrelu_kernel<<<grid, block>>>(inputs, W_ih, W_hh, b_mod,
                                        W_lin, b_lin, out);
}